// round 17
// baseline (speedup 1.0000x reference)
#include <cuda_runtime.h>
#include <cuda_fp16.h>
#include <cstdint>

#define SM_STRIDE 136            // fp16 elems per smem row (conflict-free ldmatrix)

// smem byte offsets (~46.6 KB -> 2 CTAs/SM; regs are the occupancy binder)
#define WS_OFF    0                                  // W fp16 staging: 34816
#define XS_OFF    34816                              // x fp16: 32 rows = 8704
#define XN2_OFF   (XS_OFF + 8704)                    // float[32]
#define DS_OFF    (XN2_OFF + 128)                    // float[32]
#define US_OFF    (DS_OFF + 128)                     // float[128] u = W^T h
#define HV_OFF    (US_OFF + 512)                     // float[128] h (logical)
#define HP_OFF    (HV_OFF + 512)                     // float[128] h (mma order)
#define RED1_OFF  (HP_OFF + 512)                     // float2[4][32] = 1024
#define RED2_OFF  (RED1_OFF + 1024)                  // float[4][32] = 512
#define SC_OFF    (RED2_OFF + 512)                   // float[4]
#define SMEM_BYTES (SC_OFF + 16)

#define MINN  1e-15f
#define MAXN  0.996f
#define ATLIM (1.0f - 1e-7f)

#define LDSM4(R, addr)                                                        \
    asm volatile("ldmatrix.sync.aligned.m8n8.x4.shared.b16 {%0,%1,%2,%3}, [%4];" \
                 : "=r"((R)[0]), "=r"((R)[1]), "=r"((R)[2]), "=r"((R)[3])     \
                 : "r"(addr) : "memory")

__device__ __forceinline__ void mma16816(float* d, const uint32_t* a, const uint32_t* b) {
    asm volatile(
        "mma.sync.aligned.m16n8k16.row.col.f32.f16.f16.f32 "
        "{%0,%1,%2,%3}, {%4,%5,%6,%7}, {%8,%9}, {%0,%1,%2,%3};"
        : "+f"(d[0]), "+f"(d[1]), "+f"(d[2]), "+f"(d[3])
        : "r"(a[0]), "r"(a[1]), "r"(a[2]), "r"(a[3]), "r"(b[0]), "r"(b[1]));
}

// Column permutation: thread tq's 4 owned mma cols per 16-col block are the
// logical cols {4tq..4tq+3} (contiguous) -> STG.128 epilogue.
__device__ __forceinline__ int perm_inv(int L) {   // logical -> mma position
    int blk = L & ~15;
    int t = (L >> 2) & 3;
    int u = L & 3;
    return blk + (u < 2 ? 2*t + u : 8 + 2*t + (u - 2));
}

__device__ __forceinline__ float artanh_c(float x) {
    float xc = fminf(x, ATLIM);
    return 0.5f * (log1pf(xc) - log1pf(-xc));
}

__device__ __forceinline__ void row_chain(float S2, float D, float xn2v, float y2,
                                          float& pa, float& pb, float& Lr) {
    float xn  = fmaxf(sqrtf(xn2v), MINN);
    float mxn = fmaxf(sqrtf(S2), MINN);
    float atx = artanh_c(xn);
    float r1  = tanhf(mxn / xn * atx);
    float scale1 = r1 / mxn;
    float resn = r1;
    float pn = fmaxf(resn, MINN);
    if (pn > MAXN) { scale1 *= MAXN / pn; resn = MAXN; }
    float x2 = resn * resn;
    float xy = scale1 * D;
    float num1 = 1.f + 2.f*xy + y2;
    float den  = fmaxf(1.f + 2.f*xy + x2*y2, MINN);
    float aC = num1 / den;
    float bC = (1.f - x2) / den;
    float o2n2 = aC*aC*x2 + 2.f*aC*bC*xy + bC*bC*y2;
    float o2n  = sqrtf(fmaxf(o2n2, 0.f));
    float g = 1.f;
    float pn2 = fmaxf(o2n, MINN);
    if (pn2 > MAXN) { g = MAXN / pn2; pn2 = MAXN; }
    Lr = artanh_c(pn2) / pn2;
    pa = g * aC * scale1;
    pb = g * bC;
}

__device__ __forceinline__ float final_scale(float ps, float Lr) {
    float P  = sqrtf(fmaxf(ps, 0.f));
    float un = fmaxf(Lr * P, MINN);
    float th = tanhf(un);
    float f  = th / un * Lr;
    if (th > MAXN) f *= MAXN / th;
    return f;
}

// fp32x4 -> fp16x4 (rn) into padded-stride smem
__device__ __forceinline__ void store_h16(__half* dst, int row, int col, float4 v) {
    __half2 h01 = __floats2half2_rn(v.x, v.y);
    __half2 h23 = __floats2half2_rn(v.z, v.w);
    uint2 ph;
    ph.x = *reinterpret_cast<uint32_t*>(&h01);
    ph.y = *reinterpret_cast<uint32_t*>(&h23);
    *(uint2*)(dst + row * SM_STRIDE + col) = ph;
}

__global__ void __launch_bounds__(256, 2)
blinear_fused(const float* __restrict__ X, const float* __restrict__ W,
              const float* __restrict__ B, float* __restrict__ OUT, int nTiles)
{
    extern __shared__ char smem[];
    __half* ws    = (__half*)(smem + WS_OFF);
    __half* xs    = (__half*)(smem + XS_OFF);
    float* xn2_s  = (float*)(smem + XN2_OFF);
    float* D_s    = (float*)(smem + DS_OFF);
    float* us     = (float*)(smem + US_OFF);
    float* hvec   = (float*)(smem + HV_OFF);
    float* hperm  = (float*)(smem + HP_OFF);
    float2* red1  = (float2*)(smem + RED1_OFF);  // [nq][32 rows]
    float* red2   = (float*)(smem + RED2_OFF);   // [nq][32 rows]
    float* SC     = (float*)(smem + SC_OFF);

    const int tid  = threadIdx.x;
    const int lane = tid & 31;
    const int w    = tid >> 5;   // 0..7
    const int mg   = w & 1;      // M group: rows 16*mg .. 16*mg+15
    const int nq   = w >> 1;     // N quarter: cols 32*nq .. 32*nq+31
    const int tq   = lane & 3;
    const int q    = lane >> 2;
    const int lr   = lane >> 3;  // 0..3 (load row within warp's 4)
    const int lc   = lane & 7;   // 0..7
    const int loadrow = 4 * w;   // this warp's 4 load-rows (0..31)

    // ---- once per CTA: W (128x128) -> fp16 in smem, PERMUTED row order ----
    #pragma unroll
    for (int j = 0; j < 16; ++j) {
        int row = j * 8 + w;
        float4 wv = *(const float4*)(W + (size_t)row * 128 + lane * 4);
        store_h16(ws, perm_inv(row), lane * 4, wv);
    }

    // ---- once per CTA: hyp_bias h = proj(expmap0(b)) (warp 0) ----
    if (w == 0) {
        float4 bv = *(const float4*)(B + lane * 4);
        float sq = bv.x*bv.x + bv.y*bv.y + bv.z*bv.z + bv.w*bv.w;
        #pragma unroll
        for (int o = 16; o; o >>= 1) sq += __shfl_xor_sync(0xffffffffu, sq, o);
        float bn2 = sq;
        float bn  = fmaxf(sqrtf(bn2), MINN);
        float th  = tanhf(bn);
        float hs  = th / bn;
        float hn  = hs * sqrtf(bn2);
        float pn  = fmaxf(hn, MINN);
        if (pn > MAXN) hs *= MAXN / pn;
        if (lane == 0) SC[0] = hs * hs * bn2;
        *(float4*)(hvec + lane * 4) =
            make_float4(hs*bv.x, hs*bv.y, hs*bv.z, hs*bv.w);
    }
    __syncthreads();

    const float y2 = SC[0];
    const bool hasB = (y2 != 0.0f);   // uniform across grid

    // ---- h in mma order; u = W^T h (bias path only) ----
    if (tid < 128) {
        hperm[perm_inv(tid)] = hvec[tid];
        if (hasB) {
            float a = 0.f;
            for (int j = 0; j < 128; ++j)
                a = fmaf(hvec[j], W[(size_t)j * 128 + tid], a);
            us[tid] = a;
        }
    }
    __syncthreads();

    uint32_t s_xs = (uint32_t)__cvta_generic_to_shared(xs);
    uint32_t s_ws = (uint32_t)__cvta_generic_to_shared(ws);

    // A fragment address: rows 16*mg..16*mg+15 (one m16 frag)
    const uint32_t aoff = (uint32_t)(((16*mg + (lane & 15)) * SM_STRIDE + (lane >> 4) * 8) * 2);
    // W fragments: 2 n16-groups covering this warp's 32 cols -- RESIDENT in regs
    const int bg  = lane >> 3;
    const int b_n = ((bg >> 1) << 3) + (lane & 7);
    const int b_k = (bg & 1) * 8;
    uint32_t wreg[8][2][4];
    #pragma unroll
    for (int g = 0; g < 2; ++g) {
        const uint32_t bof = (uint32_t)(((32*nq + 16*g + b_n) * SM_STRIDE + b_k) * 2);
        #pragma unroll
        for (int k = 0; k < 8; ++k)
            LDSM4(wreg[k][g], s_ws + bof + k * 32);
    }

    const int colbase = ((lc * 4) + (lr * 8)) & 31;  // float4-aligned float index

    // ================= persistent tile loop (32-row CTA tiles) ==============
    for (int tile = blockIdx.x; tile < nTiles; tile += gridDim.x) {
        const size_t tileRow = (size_t)tile * 32;
        const int row = loadrow + lr;   // this lane's load row (0..31)

        // ---- batched load: 4 LDG.128 (streaming), then convert/reduce/STS ----
        float4 xr[4];
        #pragma unroll
        for (int i = 0; i < 4; ++i)
            xr[i] = __ldcs((const float4*)(X + (tileRow + row) * 128 + colbase + 32*i));

        // L2 prefetch next tile's rows for this warp (2 KB)
        {
            int nt2 = tile + gridDim.x;
            if (nt2 < nTiles) {
                const float* pf = X + ((size_t)nt2 * 32 + loadrow) * 128 + (size_t)lane * 16;
                asm volatile("prefetch.global.L2 [%0];" :: "l"(pf));
            }
        }

        {
            float sq = 0.f, dh = 0.f;
            #pragma unroll
            for (int i = 0; i < 4; ++i) {
                const int col = colbase + 32*i;
                float4 v = xr[i];
                sq = fmaf(v.x, v.x, fmaf(v.y, v.y, fmaf(v.z, v.z, fmaf(v.w, v.w, sq))));
                if (hasB) {
                    float4 u4 = *(const float4*)(us + col);
                    dh = fmaf(v.x, u4.x, fmaf(v.y, u4.y, fmaf(v.z, u4.z, fmaf(v.w, u4.w, dh))));
                }
                store_h16(xs, row, col, v);
            }
            #pragma unroll
            for (int o = 1; o <= 4; o <<= 1) {
                sq += __shfl_xor_sync(0xffffffffu, sq, o);
                if (hasB) dh += __shfl_xor_sync(0xffffffffu, dh, o);
            }
            if (lc == 0) { xn2_s[row] = sq; D_s[row] = dh; }
        }

        __syncthreads();   // A: xs + xn2 + D visible CTA-wide

        // snapshot chain inputs (lane = tile row 0..31) before red1 reuse
        const float xn2v = xn2_s[lane];
        const float Dv   = hasB ? D_s[lane] : 0.f;

        // ---- MMA: 16 rows x 32 cols, W from registers ----
        float acc[4][4];
        #pragma unroll
        for (int nt = 0; nt < 4; ++nt)
            #pragma unroll
            for (int r = 0; r < 4; ++r) acc[nt][r] = 0.f;

        #pragma unroll
        for (int k = 0; k < 8; ++k) {
            uint32_t ah[4];
            LDSM4(ah, s_xs + aoff + k * 32);
            #pragma unroll
            for (int nt = 0; nt < 4; ++nt) {
                const int g = nt >> 1, o = (nt & 1) * 2;
                mma16816(acc[nt], ah, &wreg[k][g][o]);
            }
        }

        // ---- phase 1: per-row sum(mx^2) AND sum(relu(mx)^2); acc<-relu ----
        float sq0 = 0.f, r0 = 0.f, sq1 = 0.f, r1 = 0.f;
        #pragma unroll
        for (int nt = 0; nt < 4; ++nt) {
            float v0 = acc[nt][0], v1 = acc[nt][1];
            float v2 = acc[nt][2], v3 = acc[nt][3];
            sq0 = fmaf(v0, v0, fmaf(v1, v1, sq0));
            sq1 = fmaf(v2, v2, fmaf(v3, v3, sq1));
            float p0 = fmaxf(v0, 0.f), p1 = fmaxf(v1, 0.f);
            float p2 = fmaxf(v2, 0.f), p3 = fmaxf(v3, 0.f);
            r0 = fmaf(p0, p0, fmaf(p1, p1, r0));
            r1 = fmaf(p2, p2, fmaf(p3, p3, r1));
            if (!hasB) {
                acc[nt][0] = p0; acc[nt][1] = p1;
                acc[nt][2] = p2; acc[nt][3] = p3;
            }
        }
        #pragma unroll
        for (int o = 1; o <= 2; o <<= 1) {
            sq0 += __shfl_xor_sync(0xffffffffu, sq0, o);
            r0  += __shfl_xor_sync(0xffffffffu, r0,  o);
            sq1 += __shfl_xor_sync(0xffffffffu, sq1, o);
            r1  += __shfl_xor_sync(0xffffffffu, r1,  o);
        }
        if (tq == 0) {
            red1[nq*32 + 16*mg + q]     = make_float2(sq0, r0);
            red1[nq*32 + 16*mg + 8 + q] = make_float2(sq1, r1);
        }
        __syncthreads();   // B

        // ---- lane-parallel chain: lane = tile row; sum 4 N-quarters ----
        float S2 = 0.f, Rr = 0.f;
        #pragma unroll
        for (int n = 0; n < 4; ++n) {
            float2 e = red1[n*32 + lane];
            S2 += e.x; Rr += e.y;
        }
        float pa, pb, Lr;
        row_chain(S2, Dv, xn2v, y2, pa, pb, Lr);

        if (!hasB) {
            float fac = final_scale(pa * pa * Rr, Lr) * pa;
            #pragma unroll
            for (int rh = 0; rh < 2; ++rh) {
                const float fs = __shfl_sync(0xffffffffu, fac, 16*mg + 8*rh + q);
                float* outp = OUT + (tileRow + 16*mg + 8*rh + q) * 128
                                  + 32*nq + 4*tq;
                #pragma unroll
                for (int bl = 0; bl < 2; ++bl) {
                    float4 o;   // permuted layout: contiguous logical quad
                    o.x = fs * acc[2*bl    ][2*rh];
                    o.y = fs * acc[2*bl    ][2*rh + 1];
                    o.z = fs * acc[2*bl + 1][2*rh];
                    o.w = fs * acc[2*bl + 1][2*rh + 1];
                    __stcs((float4*)(outp + 16*bl), o);
                }
            }
        } else {
            // ---- general path: p = relu(pa*mx + pb*h), second exchange ----
            #pragma unroll
            for (int rh = 0; rh < 2; ++rh) {
                const float pav = __shfl_sync(0xffffffffu, pa, 16*mg + 8*rh + q);
                const float pbv = __shfl_sync(0xffffffffu, pb, 16*mg + 8*rh + q);
                float ps = 0.f;
                #pragma unroll
                for (int nt = 0; nt < 4; ++nt) {
                    float h0 = hperm[32*nq + 8*nt + 2*tq];
                    float h1 = hperm[32*nq + 8*nt + 2*tq + 1];
                    float p0 = fmaxf(fmaf(pav, acc[nt][2*rh],     pbv * h0), 0.f);
                    float p1 = fmaxf(fmaf(pav, acc[nt][2*rh + 1], pbv * h1), 0.f);
                    acc[nt][2*rh]     = p0;
                    acc[nt][2*rh + 1] = p1;
                    ps = fmaf(p0, p0, fmaf(p1, p1, ps));
                }
                ps += __shfl_xor_sync(0xffffffffu, ps, 1);
                ps += __shfl_xor_sync(0xffffffffu, ps, 2);
                if (tq == 0) red2[nq*32 + 16*mg + 8*rh + q] = ps;
            }
            __syncthreads();   // C (bias path only)
            float pst = 0.f;
            #pragma unroll
            for (int n = 0; n < 4; ++n) pst += red2[n*32 + lane];
            float fs_l = final_scale(pst, Lr);
            #pragma unroll
            for (int rh = 0; rh < 2; ++rh) {
                const float fs = __shfl_sync(0xffffffffu, fs_l, 16*mg + 8*rh + q);
                float* outp = OUT + (tileRow + 16*mg + 8*rh + q) * 128
                                  + 32*nq + 4*tq;
                #pragma unroll
                for (int bl = 0; bl < 2; ++bl) {
                    float4 o;
                    o.x = fs * acc[2*bl    ][2*rh];
                    o.y = fs * acc[2*bl    ][2*rh + 1];
                    o.z = fs * acc[2*bl + 1][2*rh];
                    o.w = fs * acc[2*bl + 1][2*rh + 1];
                    __stcs((float4*)(outp + 16*bl), o);
                }
            }
        }
        // cross-iteration smem reuse ordered by the CTA barriers:
        // xs/xn2/D written pre-bar-A, read pre-bar-B (snapshot) / in MMA;
        // red1/red2 written post-bar-A(t+1) which is after all chain reads of t.
    }
}

extern "C" void kernel_launch(void* const* d_in, const int* in_sizes, int n_in,
                              void* d_out, int out_size) {
    const float* x = (const float*)d_in[0];
    const float* W = (const float*)d_in[1];
    const float* b = (const float*)d_in[2];
    float* out = (float*)d_out;

    int nRows  = in_sizes[0] / 128;      // 524288
    int nTiles = nRows / 32;             // 16384

    int sms = 148;
    cudaDeviceGetAttribute(&sms, cudaDevAttrMultiProcessorCount, 0);
    int grid = 2 * sms;                  // 2 persistent CTAs per SM
    if (grid > nTiles) grid = nTiles;

    cudaFuncSetAttribute(blinear_fused,
                         cudaFuncAttributeMaxDynamicSharedMemorySize, SMEM_BYTES);
    blinear_fused<<<grid, 256, SMEM_BYTES>>>(x, W, b, out, nTiles);
}